// round 9
// baseline (speedup 1.0000x reference)
#include <cuda_runtime.h>

// SimpleTP: FullTensorProduct('1x1o','1x1o') of frac with itself, summed over N.
// = 6 quadratic moments s_ij = sum_n a_i a_j, then a fixed 9-output linear map.
//
// Warp-cooperative dense streaming: each warp owns a contiguous 768-float region
// (256 rows). Each lane loads 6 lane-contiguous float4s (dense LDG.128, 4
// wavefronts each). Role rotation handled algebraically: element e of float4
// (32k+lane) has role m=(2k+lane+e)%3; accumulate into local buckets
// r'=(2k+e)%3 (compile-time), rotate by lane%3 once at the end.
// Finalize kernel overlapped via PDL (programmatic dependent launch).

#define BLK 256
#define GRID_MAIN 592            // 148 SMs * 4 blocks (launch_bounds 256,4)
#define NACC 6
#define FULLMASK 0xffffffffu

__device__ float g_part[NACC * GRID_MAIN];

// Per-float4 products. q-rotated bucket refs passed explicitly:
//  e=0..3 target buckets r' = q, q+1, q+2, q (mod 3).
#define PROC_K(u, s0, s1, B0q, B0q1, B0q2, B1q, B1q1, B1q2, B2q, B2q1, B2q2) \
    do {                                                                     \
        B0q  = fmaf(u.x, u.x, B0q);                                          \
        B0q1 = fmaf(u.y, u.y, B0q1);                                         \
        B0q2 = fmaf(u.z, u.z, B0q2);                                         \
        B0q  = fmaf(u.w, u.w, B0q);                                          \
        B1q  = fmaf(u.x, u.y, B1q);                                          \
        B1q1 = fmaf(u.y, u.z, B1q1);                                         \
        B1q2 = fmaf(u.z, u.w, B1q2);                                         \
        B1q  = fmaf(u.w, s0,  B1q);                                          \
        B2q  = fmaf(u.x, u.z, B2q);                                          \
        B2q1 = fmaf(u.y, u.w, B2q1);                                         \
        B2q2 = fmaf(u.z, s0,  B2q2);                                         \
        B2q  = fmaf(u.w, s1,  B2q);                                          \
    } while (0)

// successor pair for k<5: shfl_down(1), lane31 patched from (k+1, lane0)
#define SUCC(uk, uk1, s0, s1)                                  \
    do {                                                       \
        s0 = __shfl_down_sync(FULLMASK, uk.x, 1);              \
        s1 = __shfl_down_sync(FULLMASK, uk.y, 1);              \
        float _b0 = __shfl_sync(FULLMASK, uk1.x, 0);           \
        float _b1 = __shfl_sync(FULLMASK, uk1.y, 0);           \
        if (lane == 31) { s0 = _b0; s1 = _b1; }                \
    } while (0)

__global__ __launch_bounds__(BLK, 4) void tp_moments_kernel(const float4* __restrict__ in4,
                                                            int num_regions) {
    // PDL: allow the dependent (finalize) kernel to begin launching now.
    asm volatile("griddepcontrol.launch_dependents;");

    const int lane = threadIdx.x & 31;
    const int gwarp = blockIdx.x * (BLK / 32) + (threadIdx.x >> 5);
    const int nwarps = gridDim.x * (BLK / 32);

    // B[d][r'] local buckets
    float B00 = 0.f, B01 = 0.f, B02 = 0.f;
    float B10 = 0.f, B11 = 0.f, B12 = 0.f;
    float B20 = 0.f, B21 = 0.f, B22 = 0.f;

    for (int R = gwarp; R < num_regions; R += nwarps) {
        const float4* base = in4 + (size_t)R * 192 + lane;
        float4 u0 = base[0];
        float4 u1 = base[32];
        float4 u2 = base[64];
        float4 u3 = base[96];
        float4 u4 = base[128];
        float4 u5 = base[160];

        float s0, s1;
        // k=0, q=0
        SUCC(u0, u1, s0, s1);
        PROC_K(u0, s0, s1, B00, B01, B02, B10, B11, B12, B20, B21, B22);
        // k=1, q=2
        SUCC(u1, u2, s0, s1);
        PROC_K(u1, s0, s1, B02, B00, B01, B12, B10, B11, B22, B20, B21);
        // k=2, q=1
        SUCC(u2, u3, s0, s1);
        PROC_K(u2, s0, s1, B01, B02, B00, B11, B12, B10, B21, B22, B20);
        // k=3, q=0
        SUCC(u3, u4, s0, s1);
        PROC_K(u3, s0, s1, B00, B01, B02, B10, B11, B12, B20, B21, B22);
        // k=4, q=2
        SUCC(u4, u5, s0, s1);
        PROC_K(u4, s0, s1, B02, B00, B01, B12, B10, B11, B22, B20, B21);
        // k=5, q=1: lane31's succ products land in junk buckets
        s0 = __shfl_down_sync(FULLMASK, u5.x, 1);
        s1 = __shfl_down_sync(FULLMASK, u5.y, 1);
        PROC_K(u5, s0, s1, B01, B02, B00, B11, B12, B10, B21, B22, B20);
    }

    // rotate local buckets to global moments: global m = (r' + lane) mod 3
    int c = lane % 3;
    float s00, s11, s22, s01, s12, s02;
    if (c == 0)      { s00 = B00; s11 = B01; s22 = B02; s01 = B10; s12 = B11; s02 = B20; }
    else if (c == 1) { s00 = B02; s11 = B00; s22 = B01; s01 = B12; s12 = B10; s02 = B22; }
    else             { s00 = B01; s11 = B02; s22 = B00; s01 = B11; s12 = B12; s02 = B21; }

    // warp reduction
    #pragma unroll
    for (int o = 16; o > 0; o >>= 1) {
        s00 += __shfl_down_sync(FULLMASK, s00, o);
        s11 += __shfl_down_sync(FULLMASK, s11, o);
        s22 += __shfl_down_sync(FULLMASK, s22, o);
        s01 += __shfl_down_sync(FULLMASK, s01, o);
        s02 += __shfl_down_sync(FULLMASK, s02, o);
        s12 += __shfl_down_sync(FULLMASK, s12, o);
    }

    __shared__ float sm[NACC][BLK / 32];
    int w = threadIdx.x >> 5;
    if (lane == 0) {
        sm[0][w] = s00; sm[1][w] = s11; sm[2][w] = s22;
        sm[3][w] = s01; sm[4][w] = s02; sm[5][w] = s12;
    }
    __syncthreads();

    if (threadIdx.x < NACC) {
        float t = 0.f;
        #pragma unroll
        for (int i = 0; i < BLK / 32; i++) t += sm[threadIdx.x][i];
        g_part[threadIdx.x * GRID_MAIN + blockIdx.x] = t;
    }
}

__global__ __launch_bounds__(BLK) void tp_finalize_kernel(const float* __restrict__ in,
                                                          int total_floats,
                                                          int num_regions,
                                                          float* __restrict__ out) {
    // PDL: wait until the primary grid's memory writes are visible.
    asm volatile("griddepcontrol.wait;" ::: "memory");

    float s[NACC];
    #pragma unroll
    for (int k = 0; k < NACC; k++) s[k] = 0.f;

    for (int b = threadIdx.x; b < GRID_MAIN; b += BLK) {
        #pragma unroll
        for (int k = 0; k < NACC; k++) s[k] += g_part[k * GRID_MAIN + b];
    }

    // tail rows beyond full regions, distributed (fixed order per thread)
    {
        int num_rows = total_floats / 3;
        int covered = num_regions * 256;
        for (int r = covered + threadIdx.x; r < num_rows; r += BLK) {
            float a = in[3 * r + 0], b = in[3 * r + 1], c = in[3 * r + 2];
            s[0] += a * a; s[1] += b * b; s[2] += c * c;
            s[3] += a * b; s[4] += a * c; s[5] += b * c;
        }
    }

    #pragma unroll
    for (int o = 16; o > 0; o >>= 1) {
        #pragma unroll
        for (int k = 0; k < NACC; k++) s[k] += __shfl_down_sync(FULLMASK, s[k], o);
    }
    __shared__ float sm[NACC][BLK / 32];
    int lane = threadIdx.x & 31;
    int w = threadIdx.x >> 5;
    if (lane == 0) {
        #pragma unroll
        for (int k = 0; k < NACC; k++) sm[k][w] = s[k];
    }
    __syncthreads();

    if (threadIdx.x == 0) {
        float t[NACC];
        #pragma unroll
        for (int k = 0; k < NACC; k++) {
            t[k] = 0.f;
            #pragma unroll
            for (int i = 0; i < BLK / 32; i++) t[k] += sm[k][i];
        }
        const float s00f = t[0], s11f = t[1], s22f = t[2];
        const float s01f = t[3], s02f = t[4], s12f = t[5];
        const float INV_SQRT3 = 0.57735026918962576f;
        const float SQRT2     = 1.41421356237309505f;
        const float INV_SQRT6 = 0.40824829046386302f;
        const float INV_SQRT2 = 0.70710678118654752f;

        out[0] = (s00f + s11f + s22f) * INV_SQRT3;        // 0e
        out[1] = 0.f;                                     // 1e: cross(x,x)=0
        out[2] = 0.f;
        out[3] = 0.f;
        out[4] = SQRT2 * s02f;                            // 2e m=-2
        out[5] = SQRT2 * s01f;                            // 2e m=-1
        out[6] = (2.f * s11f - s00f - s22f) * INV_SQRT6;  // 2e m=0
        out[7] = SQRT2 * s12f;                            // 2e m=+1
        out[8] = (s22f - s00f) * INV_SQRT2;               // 2e m=+2
    }
}

extern "C" void kernel_launch(void* const* d_in, const int* in_sizes, int n_in,
                              void* d_out, int out_size) {
    const float* frac = (const float*)d_in[0];
    float* out = (float*)d_out;
    int total_floats = in_sizes[0];              // N*3
    int num_regions = total_floats / 768;        // 768 floats = 256 rows per warp-region

    tp_moments_kernel<<<GRID_MAIN, BLK>>>((const float4*)frac, num_regions);

    // Finalize with programmatic dependent launch: overlaps its launch latency
    // with the main kernel; griddepcontrol.wait orders the data.
    cudaLaunchConfig_t cfg = {};
    cfg.gridDim = dim3(1, 1, 1);
    cfg.blockDim = dim3(BLK, 1, 1);
    cfg.dynamicSmemBytes = 0;
    cfg.stream = 0;
    cudaLaunchAttribute attr[1];
    attr[0].id = cudaLaunchAttributeProgrammaticStreamSerialization;
    attr[0].val.programmaticStreamSerializationAllowed = 1;
    cfg.attrs = attr;
    cfg.numAttrs = 1;
    cudaLaunchKernelEx(&cfg, tp_finalize_kernel, frac, total_floats, num_regions, out);
}